// round 2
// baseline (speedup 1.0000x reference)
#include <cuda_runtime.h>
#include <math_constants.h>

// Shapes fixed by the problem
#define B_  32
#define T_  12
#define N_  512
#define F_  64
#define H_  64

#define BLOCKS1 256          // 256 blocks x 8 warps x 8 pairs = 16384 = B*N
#define WARPS1  8
#define PAIRS_PER_WARP 8

// Per-block partial 12x12 gram matrices (overwritten every launch; no zeroing needed)
__device__ float g_partial[BLOCKS1 * 144];

// Kernel 1: compute sq/sk row sums and per-block partial score gram.
__global__ __launch_bounds__(256) void fft_sel_k1(
    const float* __restrict__ x,   // [B,T,N,F]
    const float* __restrict__ Wq,  // [F,H]
    const float* __restrict__ bq,  // [H]
    const float* __restrict__ Wk,  // [F,H]
    const float* __restrict__ bk)  // [H]
{
    __shared__ float s_wq[F_], s_wk[F_];
    __shared__ float s_bsum[2];
    __shared__ float s_q[64 * T_];   // 64 (b,n) pairs per block x 12 t
    __shared__ float s_k[64 * T_];

    const int tid = threadIdx.x;

    // Pre-sum weights over H (redundant per block; 16KB, L2-resident)
    if (tid < F_) {
        float aq = 0.f, ak = 0.f;
#pragma unroll
        for (int h = 0; h < H_; h++) {
            aq += Wq[tid * H_ + h];
            ak += Wk[tid * H_ + h];
        }
        s_wq[tid] = aq;
        s_wk[tid] = ak;
    } else if (tid == 64) {
        float a = 0.f;
#pragma unroll
        for (int h = 0; h < H_; h++) a += bq[h];
        s_bsum[0] = a;
    } else if (tid == 65) {
        float a = 0.f;
#pragma unroll
        for (int h = 0; h < H_; h++) a += bk[h];
        s_bsum[1] = a;
    }
    __syncthreads();

    const int wid  = tid >> 5;
    const int lane = tid & 31;
    const int half = lane >> 4;   // which of 2 rows this half-warp handles
    const int fl   = lane & 15;   // float4 index within a 64-float row

    const float4 wq4 = ((const float4*)s_wq)[fl];
    const float4 wk4 = ((const float4*)s_wk)[fl];
    const float bqs = s_bsum[0];
    const float bks = s_bsum[1];

    const int warpPairBase = (blockIdx.x * WARPS1 + wid) * PAIRS_PER_WARP;

#pragma unroll
    for (int pl = 0; pl < PAIRS_PER_WARP; pl++) {
        const int gp = warpPairBase + pl;     // global (b,n) pair
        const int b  = gp >> 9;               // /512
        const int n  = gp & 511;
        // base row for t=half of this pair; each float4 load covers fl*4..fl*4+3
        const float4* rowp =
            (const float4*)(x + ((size_t)(b * T_ + half) * N_ + n) * F_) + fl;

#pragma unroll
        for (int tt = 0; tt < T_ / 2; tt++) {
            // advance 2 time-steps per iteration: 2 * N_*F_ floats = 16384 float4
            const float4 v = rowp[(size_t)tt * (2 * N_ * F_ / 4)];
            float aq = v.x * wq4.x + v.y * wq4.y + v.z * wq4.z + v.w * wq4.w;
            float ak = v.x * wk4.x + v.y * wk4.y + v.z * wk4.z + v.w * wk4.w;
            // reduce across the 16 lanes of this half-warp
#pragma unroll
            for (int s = 8; s >= 1; s >>= 1) {
                aq += __shfl_xor_sync(0xffffffffu, aq, s);
                ak += __shfl_xor_sync(0xffffffffu, ak, s);
            }
            if (fl == 0) {
                const int t = tt * 2 + half;
                const int e = wid * PAIRS_PER_WARP + pl;   // 0..63
                s_q[e * T_ + t] = aq + bqs;
                s_k[e * T_ + t] = ak + bks;
            }
        }
    }
    __syncthreads();

    // Block-local 12x12 gram over the 64 staged (b,n) pairs
    if (tid < 144) {
        const int i = tid / 12;
        const int j = tid - i * 12;
        float acc = 0.f;
#pragma unroll 8
        for (int e = 0; e < 64; e++)
            acc += s_q[e * T_ + i] * s_k[e * T_ + j];
        g_partial[blockIdx.x * 144 + tid] = acc;
    }
}

// Kernel 2: reduce 256 partials, scale, row-wise top-k, write output.
__global__ __launch_bounds__(1024) void fft_sel_k2(float* __restrict__ out, int out_n)
{
    __shared__ float s_part[7 * 144];
    __shared__ float s_score[144];

    const int tid = threadIdx.x;
    const int g = tid / 144;
    const int p = tid - g * 144;

    if (g < 7) {
        float acc = 0.f;
#pragma unroll 8
        for (int e = g; e < BLOCKS1; e += 7)
            acc += g_partial[e * 144 + p];
        s_part[g * 144 + p] = acc;
    }
    __syncthreads();

    if (tid < 144) {
        float a = 0.f;
#pragma unroll
        for (int g2 = 0; g2 < 7; g2++) a += s_part[g2 * 144 + tid];
        // mean over (B, N, H) = / (32*512*64) = / 1048576
        s_score[tid] = a * (1.0f / 1048576.0f);
    }
    __syncthreads();

    // Output layout: [scores (T_ x tau) | indices-as-float (T_ x tau)]
    int tau;
    bool write_idx;
    if (out_n >= 2 * T_ && (out_n % (2 * T_)) == 0) {
        tau = out_n / (2 * T_);
        write_idx = true;
    } else {
        tau = out_n / T_;
        write_idx = false;
    }
    if (tau > T_) tau = T_;

    if (tid < T_) {
        const int i = tid;
        float v[T_];
#pragma unroll
        for (int j = 0; j < T_; j++) v[j] = s_score[i * 12 + j];
        unsigned usedmask = 0u;
        for (int r = 0; r < tau; r++) {
            float best = -CUDART_INF_F;
            int bj = 0;
#pragma unroll
            for (int j = 0; j < T_; j++) {
                // strict > : first occurrence wins ties (matches jax top_k)
                bool ok = ((usedmask >> j) & 1u) == 0u && v[j] > best;
                if (ok) { best = v[j]; bj = j; }
            }
            usedmask |= (1u << bj);
            out[i * tau + r] = best;
            if (write_idx) out[T_ * tau + i * tau + r] = (float)bj;
        }
    }
}

extern "C" void kernel_launch(void* const* d_in, const int* in_sizes, int n_in,
                              void* d_out, int out_size)
{
    const float* x  = (const float*)d_in[0];
    const float* Wq = (const float*)d_in[1];
    const float* bq = (const float*)d_in[2];
    const float* Wk = (const float*)d_in[3];
    const float* bk = (const float*)d_in[4];
    (void)in_sizes; (void)n_in;

    fft_sel_k1<<<BLOCKS1, 256>>>(x, Wq, bq, Wk, bk);
    fft_sel_k2<<<1, 1024>>>((float*)d_out, out_size);
}